// round 2
// baseline (speedup 1.0000x reference)
#include <cuda_runtime.h>
#include <cuda_bf16.h>
#include <cstdint>

// Problem constants (fixed by the reference)
#define MAXN 100000
#define MAXE 1600000
#define NPB 8          // nodes per block in the layer kernel (1 warp per node)

// ---------------- device scratch (no allocations allowed) ----------------
__device__ float g_deg[MAXN];
__device__ int   g_cnt[MAXN];
__device__ float g_dinv[MAXN];
__device__ float g_selfnorm[MAXN];
__device__ int   g_off[MAXN + 1];
__device__ int   g_cur[MAXN];
__device__ int   g_bsums[256];
__device__ int   g_csr_src[MAXE];
__device__ float g_csr_norm[MAXE];
__device__ float g_bufA[(size_t)MAXN * 80];
__device__ float g_bufB[(size_t)MAXN * 80];

// ---------------- preprocessing kernels ----------------
__global__ void k_init(int n) {
    int i = blockIdx.x * blockDim.x + threadIdx.x;
    if (i < n) { g_deg[i] = 1.0f; g_cnt[i] = 0; }
}

// NOTE: edge_index is int32 on device (JAX default x64-disabled demotes int64).
__global__ void k_edge_deg(int ecnt, const int* __restrict__ ei,
                           const float* __restrict__ ew) {
    int e = blockIdx.x * blockDim.x + threadIdx.x;
    if (e < ecnt) {
        int d = ei[ecnt + e];   // dst row
        atomicAdd(&g_deg[d], ew[e]);
        atomicAdd(&g_cnt[d], 1);
    }
}

__global__ void k_dinv(int n) {
    int i = blockIdx.x * blockDim.x + threadIdx.x;
    if (i < n) {
        float di = rsqrtf(g_deg[i]);   // deg >= 1 always (self loop fill 1.0)
        g_dinv[i] = di;
        g_selfnorm[i] = di * di;
    }
}

// Block-wise Hillis-Steele exclusive scan (1024 elems / block)
__global__ void k_scan1(int n) {
    __shared__ int sh[1024];
    int tid = threadIdx.x;
    int i = blockIdx.x * 1024 + tid;
    int v = (i < n) ? g_cnt[i] : 0;
    sh[tid] = v;
    __syncthreads();
    for (int off = 1; off < 1024; off <<= 1) {
        int t = (tid >= off) ? sh[tid - off] : 0;
        __syncthreads();
        sh[tid] += t;
        __syncthreads();
    }
    int incl = sh[tid];
    if (i < n) g_off[i] = incl - v;           // exclusive (partial)
    if (tid == 1023) g_bsums[blockIdx.x] = incl;
}

__global__ void k_scan2(int nb, int n) {
    if (threadIdx.x == 0 && blockIdx.x == 0) {
        int run = 0;
        for (int k = 0; k < nb; k++) { int t = g_bsums[k]; g_bsums[k] = run; run += t; }
        g_off[n] = run;   // = E
    }
}

__global__ void k_scan3(int n) {
    int i = blockIdx.x * blockDim.x + threadIdx.x;
    if (i < n) {
        int o = g_off[i] + g_bsums[i >> 10];
        g_off[i] = o;
        g_cur[i] = o;
    }
}

__global__ void k_scatter(int ecnt, const int* __restrict__ ei,
                          const float* __restrict__ ew) {
    int e = blockIdx.x * blockDim.x + threadIdx.x;
    if (e < ecnt) {
        int s = ei[e];
        int d = ei[ecnt + e];
        int pos = atomicAdd(&g_cur[d], 1);
        g_csr_src[pos] = s;
        g_csr_norm[pos] = g_dinv[s] * ew[e] * g_dinv[d];
    }
}

// ---------------- fused GCN layer: out = (A x) W + b  (optional relu) ----------------
// Uses A(xW) = (Ax)W: aggregate FIRST on the narrower input features, then dense matmul.
// Phase 1: one warp per node gathers z = self_norm*x[node] + sum_e norm*x[src] into smem.
// Phase 2: block computes dense z @ W + b with W in smem.
template<int F_IN, int F_OUT, bool RELU>
__global__ void k_layer(int n, int sel_in, int sel_out,
                        const float* __restrict__ ext_in, float* ext_out,
                        const float* __restrict__ W, const float* __restrict__ b) {
    __shared__ float sW[F_IN * F_OUT];
    __shared__ float sb[F_OUT];
    __shared__ float sz[NPB][F_IN];

    const float* in = (sel_in == 0) ? g_bufA : (sel_in == 1) ? g_bufB : ext_in;
    float* out = (sel_out == 0) ? g_bufA : (sel_out == 1) ? g_bufB : ext_out;

    for (int k = threadIdx.x; k < F_IN * F_OUT; k += blockDim.x) sW[k] = W[k];
    for (int k = threadIdx.x; k < F_OUT; k += blockDim.x) sb[k] = b[k];

    int warp = threadIdx.x >> 5;
    int lane = threadIdx.x & 31;
    int node = blockIdx.x * NPB + warp;

    if (node < n) {
        int e0 = g_off[node];
        int e1 = g_off[node + 1];
        if constexpr (F_IN == 1) {
            // edge-parallel over lanes, warp reduce
            float acc = (lane == 0) ? g_selfnorm[node] * in[node] : 0.0f;
            for (int e = e0 + lane; e < e1; e += 32)
                acc += g_csr_norm[e] * __ldg(&in[g_csr_src[e]]);
            #pragma unroll
            for (int o = 16; o; o >>= 1) acc += __shfl_xor_sync(0xffffffffu, acc, o);
            if (lane == 0) sz[warp][0] = acc;
        } else {
            constexpr int FPL = (F_IN + 31) / 32;
            float acc[FPL];
            float sn = g_selfnorm[node];
            #pragma unroll
            for (int r = 0; r < FPL; r++) {
                int f = lane + 32 * r;
                acc[r] = (f < F_IN) ? sn * in[(size_t)node * F_IN + f] : 0.0f;
            }
            for (int e = e0; e < e1; e++) {
                int s = g_csr_src[e];
                float c = g_csr_norm[e];
                const float* xr = in + (size_t)s * F_IN;
                #pragma unroll
                for (int r = 0; r < FPL; r++) {
                    int f = lane + 32 * r;
                    if (f < F_IN) acc[r] += c * __ldg(xr + f);
                }
            }
            #pragma unroll
            for (int r = 0; r < FPL; r++) {
                int f = lane + 32 * r;
                if (f < F_IN) sz[warp][f] = acc[r];
            }
        }
    }
    __syncthreads();

    // Phase 2: NPB*F_OUT outputs per block
    for (int idx = threadIdx.x; idx < NPB * F_OUT; idx += blockDim.x) {
        int wnode = idx / F_OUT;
        int j = idx - wnode * F_OUT;
        int nd = blockIdx.x * NPB + wnode;
        if (nd < n) {
            float a = sb[j];
            #pragma unroll 4
            for (int f = 0; f < F_IN; f++) a += sz[wnode][f] * sW[f * F_OUT + j];
            if (RELU) a = fmaxf(a, 0.0f);
            out[(size_t)nd * F_OUT + j] = a;
        }
    }
}

// ---------------- launch ----------------
extern "C" void kernel_launch(void* const* d_in, const int* in_sizes, int n_in,
                              void* d_out, int out_size) {
    const float* x  = (const float*)d_in[0];
    const int*   ei = (const int*)d_in[1];     // int32! (JAX demotes int64)
    const float* ew = (const float*)d_in[2];
    const float* W1 = (const float*)d_in[3];  const float* b1 = (const float*)d_in[4];
    const float* W2 = (const float*)d_in[5];  const float* b2 = (const float*)d_in[6];
    const float* W3 = (const float*)d_in[7];  const float* b3 = (const float*)d_in[8];
    const float* W4 = (const float*)d_in[9];  const float* b4 = (const float*)d_in[10];
    const float* W5 = (const float*)d_in[11]; const float* b5 = (const float*)d_in[12];
    float* out = (float*)d_out;

    int n = in_sizes[0];       // x is [N,1]
    int e = in_sizes[2];       // edge_weights is [E]

    int tb = 256;
    int gbN = (n + tb - 1) / tb;
    int gbE = (e + tb - 1) / tb;
    int nb  = (n + 1023) / 1024;

    // degree + count
    k_init<<<gbN, tb>>>(n);
    k_edge_deg<<<gbE, tb>>>(e, ei, ew);
    k_dinv<<<gbN, tb>>>(n);

    // CSR build (counting sort by dst)
    k_scan1<<<nb, 1024>>>(n);
    k_scan2<<<1, 32>>>(nb, n);
    k_scan3<<<gbN, tb>>>(n);
    k_scatter<<<gbE, tb>>>(e, ei, ew);

    // 5 fused layers: ping-pong bufA/bufB; last writes relu to d_out
    int gbL = (n + NPB - 1) / NPB;
    k_layer<1,  20,  false><<<gbL, 256>>>(n, 2, 0, x,       nullptr, W1, b1);
    k_layer<20, 40,  false><<<gbL, 256>>>(n, 0, 1, nullptr, nullptr, W2, b2);
    k_layer<40, 60,  false><<<gbL, 256>>>(n, 1, 0, nullptr, nullptr, W3, b3);
    k_layer<60, 80,  false><<<gbL, 256>>>(n, 0, 1, nullptr, nullptr, W4, b4);
    k_layer<80, 100, true ><<<gbL, 256>>>(n, 1, 2, nullptr, out,     W5, b5);
    (void)n_in; (void)out_size;
}